// round 6
// baseline (speedup 1.0000x reference)
#include <cuda_runtime.h>

typedef unsigned long long u64;

// ---------------- problem constants ----------------
constexpr int B_   = 8;
constexpr int N0_  = 50000;
constexpr int N1_  = 12500;
constexpr int E_   = 400000;
constexpr int FIN_ = 3;
constexpr int C_   = 32;
constexpr int K_   = 6;
constexpr int Z_   = 128;
constexpr int DOWN_NNZ_ = N1_ * 4;
constexpr int UP_NNZ_   = N0_ * 3;

// ---------------- device scratch (static, no runtime alloc) ----------------
__device__ float g_buf[4][(size_t)B_ * N0_ * C_];     // T ring (3) + acc (1)
__device__ float g_S[5][(size_t)B_ * N0_ * FIN_];     // encoder T1..T5 (3ch)
__device__ float g_h[(size_t)B_ * N0_ * C_];          // encoder conv output
__device__ float g_hc[(size_t)B_ * N1_ * C_];         // down-pooled
__device__ float g_hc2[(size_t)B_ * N1_ * C_];        // decoder linear output
__device__ float g_z[B_ * Z_];                        // latent
__device__ int   g_rowptr[N0_ + 1];
__device__ int   g_cnt[N0_];                          // in-degree counts (zeroed at END of each call)
__device__ int   g_cur[N0_ + 1];                      // fill cursor
__device__ int   g_srcs[E_];
__device__ float g_norms[E_];

// ---------------- f32x2 helpers ----------------
__device__ __forceinline__ u64 pack2(float x, float y) {
    u64 r; asm("mov.b64 %0,{%1,%2};" : "=l"(r) : "f"(x), "f"(y)); return r;
}
__device__ __forceinline__ void fma2(u64& acc, u64 a, u64 b) {
    asm("fma.rn.f32x2 %0,%1,%2,%0;" : "+l"(acc) : "l"(a), "l"(b));
}
__device__ __forceinline__ float2 unpack2(u64 v) {
    float2 f; asm("mov.b64 {%0,%1},%2;" : "=f"(f.x), "=f"(f.y) : "l"(v)); return f;
}

// ---------------- CSR build (g_cnt must be zero at entry; restored at call end) ----------------
__global__ void k_count(const int* __restrict__ dst) {
    int e = blockIdx.x * blockDim.x + threadIdx.x;
    if (e < E_) atomicAdd(&g_cnt[dst[e]], 1);
}

__global__ void k_scan() {
    __shared__ int wsum[32];
    __shared__ int carry;
    int t = threadIdx.x;  // 1024 threads
    if (t == 0) carry = 0;
    __syncthreads();
    for (int base = 0; base < N0_; base += 1024) {
        int i = base + t;
        int v = (i < N0_) ? g_cnt[i] : 0;
        int x = v;
#pragma unroll
        for (int d = 1; d < 32; d <<= 1) {
            int y = __shfl_up_sync(0xffffffffu, x, d);
            if ((t & 31) >= d) x += y;
        }
        if ((t & 31) == 31) wsum[t >> 5] = x;
        __syncthreads();
        if (t < 32) {
            int w = wsum[t];
#pragma unroll
            for (int d = 1; d < 32; d <<= 1) {
                int y = __shfl_up_sync(0xffffffffu, w, d);
                if (t >= d) w += y;
            }
            wsum[t] = w;
        }
        __syncthreads();
        int add  = (t >= 32) ? wsum[(t >> 5) - 1] : 0;
        int incl = x + add + carry;
        if (i < N0_) { g_rowptr[i + 1] = incl; g_cur[i + 1] = incl; }
        __syncthreads();
        if (t == 1023) carry = incl;
        __syncthreads();
    }
    if (t == 0) { g_rowptr[0] = 0; g_cur[0] = 0; }
}

__global__ void k_fill(const int* __restrict__ src, const int* __restrict__ dst,
                       const float* __restrict__ norm) {
    int e = blockIdx.x * blockDim.x + threadIdx.x;
    if (e < E_) {
        int d = dst[e];
        int pos = atomicAdd(&g_cur[d], 1);
        g_srcs[pos]  = src[e];
        g_norms[pos] = norm[e];
    }
}

__global__ void k_zero_cnt() {
    int i = blockIdx.x * blockDim.x + threadIdx.x;
    if (i < N0_) g_cnt[i] = 0;
}

// ---------------- encoder conv (Cin=3), unfused propagate ----------------
// prev_idx: -1 => x ; pp_idx: -2 => first-k (T1 = prop(x)); -1 => x ; else g_S idx
__global__ void enc_prop(const float* __restrict__ x, int prev_idx, int pp_idx, int next_idx) {
    int w = (blockIdx.x * blockDim.x + threadIdx.x) >> 5;
    if (w >= N0_) return;
    int lane = threadIdx.x & 31;
    int b = lane / 3;
    int c = lane - 3 * b;
    bool act = lane < (B_ * FIN_);
    const float* prev = (prev_idx < 0) ? x : g_S[prev_idx];
    bool k1 = (pp_idx == -2);
    const float* pp = k1 ? nullptr : ((pp_idx < 0) ? x : g_S[pp_idx]);

    int beg = g_rowptr[w], end = g_rowptr[w + 1];
    float s = 0.f;
    for (int p0 = beg; p0 < end; p0 += 32) {
        int p = p0 + lane;
        int se = 0; float ne = 0.f;
        if (p < end) { se = g_srcs[p]; ne = g_norms[p]; }
        int cnt = min(32, end - p0);
        for (int j = 0; j < cnt; j++) {
            int   sj = __shfl_sync(0xffffffffu, se, j);
            float nj = __shfl_sync(0xffffffffu, ne, j);
            if (act) s += nj * prev[(b * N0_ + sj) * FIN_ + c];
        }
    }
    if (act) {
        int idx = (b * N0_ + w) * FIN_ + c;
        float tk = k1 ? s : 2.f * s - pp[idx];
        g_S[next_idx][idx] = tk;
    }
}

__global__ void enc_combine(const float* __restrict__ x, const float* __restrict__ Wenc,
                            const float* __restrict__ benc) {
    __shared__ float Wsm[K_ * FIN_ * C_];
    __shared__ float bsm[C_];
    int t = threadIdx.x;
    for (int i = t; i < K_ * FIN_ * C_; i += blockDim.x) Wsm[i] = Wenc[i];
    if (t < C_) bsm[t] = benc[t];
    __syncthreads();
    int w = (blockIdx.x * blockDim.x + t) >> 5;
    if (w >= N0_) return;
    int lane = t & 31;
#pragma unroll
    for (int b = 0; b < B_; b++) {
        float a = bsm[lane];
#pragma unroll
        for (int kc = 0; kc < K_ * FIN_; kc++) {
            int k = kc / 3, c = kc - 3 * (kc / 3);
            float v = (k == 0) ? x[(b * N0_ + w) * FIN_ + c]
                               : g_S[k - 1][(b * N0_ + w) * FIN_ + c];
            a += v * Wsm[kc * C_ + lane];
        }
        g_h[(b * N0_ + w) * C_ + lane] = fmaxf(a, 0.f);
    }
}

// ---------------- pools ----------------
__global__ void down_pool(const int* __restrict__ dcol, const float* __restrict__ dval) {
    int wi = (blockIdx.x * blockDim.x + threadIdx.x) >> 5;
    if (wi >= B_ * N1_) return;
    int lane = threadIdx.x & 31;
    int b = wi / N1_, r = wi - b * N1_;
    float a = 0.f;
#pragma unroll
    for (int j = 0; j < 4; j++) {
        int   col = dcol[4 * r + j];
        float v   = dval[4 * r + j];
        a += v * g_h[(b * N0_ + col) * C_ + lane];
    }
    g_hc[(b * N1_ + r) * C_ + lane] = a;
}

__global__ void up_pool(const int* __restrict__ ucol, const float* __restrict__ uval) {
    int wi = (blockIdx.x * blockDim.x + threadIdx.x) >> 5;
    if (wi >= B_ * N0_) return;
    int lane = threadIdx.x & 31;
    int b = wi / N0_, i = wi - b * N0_;
    float a = 0.f;
#pragma unroll
    for (int j = 0; j < 3; j++) {
        int   col = ucol[3 * i + j];
        float v   = uval[3 * i + j];
        a += v * g_hc2[(b * N1_ + col) * C_ + lane];
    }
    g_buf[0][(b * N0_ + i) * C_ + lane] = a;
}

// ---------------- dense linears ----------------
__global__ void enc_lin_init(const float* __restrict__ bias) {
    int t = blockIdx.x * blockDim.x + threadIdx.x;
    if (t < B_ * Z_) g_z[t] = bias[t & (Z_ - 1)];
}

// 256 threads: z = t&127 output channel, h2 = t>>7 selects batches [4*h2, 4*h2+4)
__global__ void enc_lin(const float* __restrict__ We) {
    constexpr int SLAB = 512;
    __shared__ float hs[B_][SLAB];
    int base = blockIdx.x * SLAB;
    int t = threadIdx.x;
    int z = t & 127, h2 = t >> 7;
    for (int idx = t; idx < B_ * SLAB; idx += 256) {
        int b = idx >> 9, kk = idx & (SLAB - 1);
        int g = base + kk;
        hs[b][kk] = (g < N1_ * C_) ? g_hc[b * (N1_ * C_) + g] : 0.f;
    }
    __syncthreads();
    int lim = min(SLAB, N1_ * C_ - base);
    float a0 = 0.f, a1 = 0.f, a2 = 0.f, a3 = 0.f;
    int bb = h2 * 4;
#pragma unroll 8
    for (int kk = 0; kk < lim; kk++) {
        float w = __ldg(We + (size_t)(base + kk) * Z_ + z);
        a0 = fmaf(hs[bb + 0][kk], w, a0);
        a1 = fmaf(hs[bb + 1][kk], w, a1);
        a2 = fmaf(hs[bb + 2][kk], w, a2);
        a3 = fmaf(hs[bb + 3][kk], w, a3);
    }
    atomicAdd(&g_z[(bb + 0) * Z_ + z], a0);
    atomicAdd(&g_z[(bb + 1) * Z_ + z], a1);
    atomicAdd(&g_z[(bb + 2) * Z_ + z], a2);
    atomicAdd(&g_z[(bb + 3) * Z_ + z], a3);
}

// thread-per-float4-of-j; all 8 batches in registers; streams Wd once at high MLP
__global__ void __launch_bounds__(256) dec_lin(const float* __restrict__ Wd,
                                               const float* __restrict__ bd) {
    __shared__ float zsm[B_ * Z_];
    int t = threadIdx.x;
    for (int i = t; i < B_ * Z_; i += 256) zsm[i] = g_z[i];
    __syncthreads();
    constexpr int J4 = N1_ * C_ / 4;   // 100000 float4 columns
    int j4 = blockIdx.x * 256 + t;
    if (j4 >= J4) return;
    const float4* W4 = (const float4*)Wd;
    float4 bias = ((const float4*)bd)[j4];
    float4 a[B_];
#pragma unroll
    for (int b = 0; b < B_; b++) a[b] = bias;
#pragma unroll 4
    for (int zk = 0; zk < Z_; zk++) {
        float4 w = __ldg(W4 + (size_t)zk * J4 + j4);
#pragma unroll
        for (int b = 0; b < B_; b++) {
            float zv = zsm[b * Z_ + zk];
            a[b].x = fmaf(zv, w.x, a[b].x);
            a[b].y = fmaf(zv, w.y, a[b].y);
            a[b].z = fmaf(zv, w.z, a[b].z);
            a[b].w = fmaf(zv, w.w, a[b].w);
        }
    }
    float4* out4 = (float4*)g_hc2;
#pragma unroll
    for (int b = 0; b < B_; b++) {
        float4 r = a[b];
        r.x = fmaxf(r.x, 0.f); r.y = fmaxf(r.y, 0.f);
        r.z = fmaxf(r.z, 0.f); r.w = fmaxf(r.w, 0.f);
        out4[(size_t)b * J4 + j4] = r;
    }
}

// ---------------- decoder Cheb conv: k=0 term (smem + f32x2 epilogue) ----------------
template <int COUT, bool HASBIAS>
__global__ void __launch_bounds__(256) conv_k0(
    int t0_idx, float* __restrict__ out3,
    const float* __restrict__ Wk, const float* __restrict__ bias) {
    __shared__ __align__(16) float tkbuf[8][256];
    int w = (blockIdx.x * blockDim.x + threadIdx.x) >> 5;
    if (w >= N0_) return;
    int lane = threadIdx.x & 31;
    int warp = threadIdx.x >> 5;
    bool vlane = lane < COUT;
    u64 w2p[16];
#pragma unroll
    for (int i = 0; i < 16; i++)
        w2p[i] = vlane ? pack2(Wk[(2 * i) * COUT + lane], Wk[(2 * i + 1) * COUT + lane]) : 0ull;
    const float* T0 = g_buf[t0_idx];
#pragma unroll
    for (int b = 0; b < B_; b++)
        tkbuf[warp][b * 32 + lane] = T0[(b * N0_ + w) * C_ + lane];
    __syncwarp();
    float* acc = (COUT == C_) ? g_buf[3] : out3;
#pragma unroll
    for (int b = 0; b < B_; b++) {
        const u64* tb = (const u64*)&tkbuf[warp][b * 32];
        u64 a2 = 0;
#pragma unroll
        for (int i = 0; i < 16; i++) fma2(a2, tb[i], w2p[i]);
        float2 cc = unpack2(a2);
        float contrib = cc.x + cc.y;
        if (vlane)
            acc[(b * N0_ + w) * COUT + lane] = (HASBIAS ? bias[lane] : 0.f) + contrib;
    }
}

// ---------------- fused Cheb step: Tk = 2*prop(Tprev) - Tpp ; acc += Tk @ W[k] ----------------
// gridDim.y = 2: each warp handles 4 of the 8 batches. Gather 4-edge unrolled (16 LDG in flight).
template <int COUT, bool K1, bool WRITE_T, bool RELU_OUT>
__global__ void __launch_bounds__(256) cheb_step(
    int prev_idx, int pp_idx, int next_idx, int out_idx,
    float* __restrict__ acc3, const float* __restrict__ Wk) {
    __shared__ __align__(16) float tkbuf[8][128];
    int w = (blockIdx.x * blockDim.x + threadIdx.x) >> 5;
    if (w >= N0_) return;
    int lane = threadIdx.x & 31;
    int warp = threadIdx.x >> 5;
    int b0 = blockIdx.y * 4;             // batch offset for this warp
    bool vlane = lane < COUT;
    u64 w2p[16];
#pragma unroll
    for (int i = 0; i < 16; i++)
        w2p[i] = vlane ? pack2(Wk[(2 * i) * COUT + lane], Wk[(2 * i + 1) * COUT + lane]) : 0ull;

    const float* Tprev = g_buf[prev_idx] + (size_t)b0 * N0_ * C_;
    const float* Tpp   = K1 ? nullptr : g_buf[pp_idx];

    int beg = g_rowptr[w], end = g_rowptr[w + 1];
    float s[4];
#pragma unroll
    for (int b = 0; b < 4; b++) s[b] = 0.f;

    for (int p0 = beg; p0 < end; p0 += 32) {
        int p = p0 + lane;
        int se = 0; float ne = 0.f;
        if (p < end) { se = g_srcs[p]; ne = g_norms[p]; }
        int cnt = min(32, end - p0);
        int j = 0;
        for (; j + 4 <= cnt; j += 4) {
            int   v0 = __shfl_sync(0xffffffffu, se, j);
            int   v1 = __shfl_sync(0xffffffffu, se, j + 1);
            int   v2 = __shfl_sync(0xffffffffu, se, j + 2);
            int   v3 = __shfl_sync(0xffffffffu, se, j + 3);
            float n0 = __shfl_sync(0xffffffffu, ne, j);
            float n1 = __shfl_sync(0xffffffffu, ne, j + 1);
            float n2 = __shfl_sync(0xffffffffu, ne, j + 2);
            float n3 = __shfl_sync(0xffffffffu, ne, j + 3);
            const float* q0 = Tprev + (size_t)v0 * C_ + lane;
            const float* q1 = Tprev + (size_t)v1 * C_ + lane;
            const float* q2 = Tprev + (size_t)v2 * C_ + lane;
            const float* q3 = Tprev + (size_t)v3 * C_ + lane;
            float a0[4], a1[4], a2[4], a3[4];
#pragma unroll
            for (int b = 0; b < 4; b++) a0[b] = __ldg(q0 + (size_t)b * N0_ * C_);
#pragma unroll
            for (int b = 0; b < 4; b++) a1[b] = __ldg(q1 + (size_t)b * N0_ * C_);
#pragma unroll
            for (int b = 0; b < 4; b++) a2[b] = __ldg(q2 + (size_t)b * N0_ * C_);
#pragma unroll
            for (int b = 0; b < 4; b++) a3[b] = __ldg(q3 + (size_t)b * N0_ * C_);
#pragma unroll
            for (int b = 0; b < 4; b++) {
                s[b] = fmaf(n0, a0[b], s[b]);
                s[b] = fmaf(n1, a1[b], s[b]);
                s[b] = fmaf(n2, a2[b], s[b]);
                s[b] = fmaf(n3, a3[b], s[b]);
            }
        }
        for (; j < cnt; j++) {
            int   v0 = __shfl_sync(0xffffffffu, se, j);
            float n0 = __shfl_sync(0xffffffffu, ne, j);
            const float* q0 = Tprev + (size_t)v0 * C_ + lane;
#pragma unroll
            for (int b = 0; b < 4; b++)
                s[b] = fmaf(n0, __ldg(q0 + (size_t)b * N0_ * C_), s[b]);
        }
    }

    // ---- recursion + stage T_k into smem (and write T_k if needed) ----
    float* Tnext = WRITE_T ? g_buf[next_idx] : nullptr;
#pragma unroll
    for (int b = 0; b < 4; b++) {
        int base = ((b0 + b) * N0_ + w) * C_;
        float tk = K1 ? s[b] : 2.f * s[b] - Tpp[base + lane];
        if (WRITE_T) Tnext[base + lane] = tk;
        tkbuf[warp][b * 32 + lane] = tk;
    }
    __syncwarp();

    // ---- epilogue (f32x2): contrib[b][cout=lane] = sum_c tk[b][c] * W[c][cout] ----
    float* acc  = (COUT == C_) ? g_buf[3] : acc3;
    float* outp = RELU_OUT ? g_buf[out_idx] : nullptr;
#pragma unroll
    for (int b = 0; b < 4; b++) {
        const u64* tb = (const u64*)&tkbuf[warp][b * 32];
        u64 a2 = 0;
#pragma unroll
        for (int i = 0; i < 16; i++) fma2(a2, tb[i], w2p[i]);
        float2 cc = unpack2(a2);
        float contrib = cc.x + cc.y;
        if (RELU_OUT) {
            int base = ((b0 + b) * N0_ + w) * C_;
            float v = acc[base + lane] + contrib;   // COUT==32 here
            outp[base + lane] = fmaxf(v, 0.f);
        } else if (vlane) {
            acc[((b0 + b) * N0_ + w) * COUT + lane] += contrib;
        }
    }
}

// ---------------- launch ----------------
extern "C" void kernel_launch(void* const* d_in, const int* in_sizes, int n_in,
                              void* d_out, int out_size) {
    (void)in_sizes; (void)n_in; (void)out_size;
    const float* x      = (const float*)d_in[0];
    const int*   eidx   = (const int*)  d_in[1];
    const float* Anorm  = (const float*)d_in[2];
    const int*   didx   = (const int*)  d_in[3];
    const float* dval   = (const float*)d_in[4];
    const int*   uidx   = (const int*)  d_in[5];
    const float* uval   = (const float*)d_in[6];
    const float* Wenc0  = (const float*)d_in[7];
    const float* benc0  = (const float*)d_in[8];
    const float* Wdec0  = (const float*)d_in[9];
    const float* bdec0  = (const float*)d_in[10];
    const float* Wdec1  = (const float*)d_in[11];
    const float* encW   = (const float*)d_in[12];
    const float* encb   = (const float*)d_in[13];
    const float* decW   = (const float*)d_in[14];
    const float* decb   = (const float*)d_in[15];
    float* out = (float*)d_out;

    const int GPV  = N0_ * 32 / 256;          // 6250: warp-per-vertex grids
    const dim3 GPV2(GPV, 2);                  // batch-split grids
    const int GE   = (E_ + 255) / 256;        // 1563
    const int GN0  = (N0_ + 255) / 256;       // 196

    // CSR by dst (g_cnt is zero at entry; re-zeroed at end of this call)
    k_count<<<GE, 256>>>(eidx + E_);
    k_scan<<<1, 1024>>>();
    k_fill<<<GE, 256>>>(eidx, eidx + E_, Anorm);

    // ---- encoder conv (Cin=3) ----   (first enc_prop = launch index 3; idx 5 = ncu canary)
    enc_prop<<<GPV, 256>>>(x, -1, -2, 0);   // T1
    enc_prop<<<GPV, 256>>>(x,  0, -1, 1);   // T2
    enc_prop<<<GPV, 256>>>(x,  1,  0, 2);   // T3
    enc_prop<<<GPV, 256>>>(x,  2,  1, 3);   // T4
    enc_prop<<<GPV, 256>>>(x,  3,  2, 4);   // T5
    enc_combine<<<GPV, 256>>>(x, Wenc0, benc0);

    // ---- down pool ----
    down_pool<<<B_ * N1_ * 32 / 256, 256>>>(didx + DOWN_NNZ_, dval);

    // ---- encoder linear ----
    enc_lin_init<<<(B_ * Z_ + 255) / 256, 256>>>(encb);
    enc_lin<<<(N1_ * C_ + 511) / 512, 256>>>(encW);

    // ---- decoder linear (+relu) ----
    dec_lin<<<(N1_ * C_ / 4 + 255) / 256, 256>>>(decW, decb);

    // ---- up pool -> g_buf[0] ----
    up_pool<<<B_ * N0_ * 32 / 256, 256>>>(uidx + UP_NNZ_, uval);

    // ---- decoder conv0 (32->32, bias, relu). acc = g_buf[3]; ring 0/1/2 ----
    conv_k0<32, true><<<GPV, 256>>>(0, nullptr, Wdec0, bdec0);
    cheb_step<32, true , true , false><<<GPV2, 256>>>(0, 0, 1, 0, nullptr, Wdec0 + 1 * C_ * C_);
    cheb_step<32, false, true , false><<<GPV2, 256>>>(1, 0, 2, 0, nullptr, Wdec0 + 2 * C_ * C_);
    cheb_step<32, false, true , false><<<GPV2, 256>>>(2, 1, 0, 0, nullptr, Wdec0 + 3 * C_ * C_);
    cheb_step<32, false, true , false><<<GPV2, 256>>>(0, 2, 1, 0, nullptr, Wdec0 + 4 * C_ * C_);
    cheb_step<32, false, false, true ><<<GPV2, 256>>>(1, 0, 0, 2, nullptr, Wdec0 + 5 * C_ * C_); // relu -> buf2

    // ---- decoder conv1 (32->3, no bias). acc = d_out; T0 = buf2 ----
    conv_k0<3, false><<<GPV, 256>>>(2, out, Wdec1, nullptr);
    cheb_step<3, true , true , false><<<GPV2, 256>>>(2, 0, 0, 0, out, Wdec1 + 1 * C_ * FIN_);
    cheb_step<3, false, true , false><<<GPV2, 256>>>(0, 2, 1, 0, out, Wdec1 + 2 * C_ * FIN_);
    cheb_step<3, false, true , false><<<GPV2, 256>>>(1, 0, 2, 0, out, Wdec1 + 3 * C_ * FIN_);
    cheb_step<3, false, true , false><<<GPV2, 256>>>(2, 1, 0, 0, out, Wdec1 + 4 * C_ * FIN_);
    cheb_step<3, false, false, false><<<GPV2, 256>>>(0, 2, 0, 0, out, Wdec1 + 5 * C_ * FIN_);

    // restore g_cnt = 0 for the next call (keeps every call identical)
    k_zero_cnt<<<GN0, 256>>>();
}

// round 7
// speedup vs baseline: 1.3371x; 1.3371x over previous
#include <cuda_runtime.h>

typedef unsigned long long u64;

// ---------------- problem constants ----------------
constexpr int B_   = 8;
constexpr int N0_  = 50000;
constexpr int N1_  = 12500;
constexpr int E_   = 400000;
constexpr int FIN_ = 3;
constexpr int C_   = 32;
constexpr int K_   = 6;
constexpr int Z_   = 128;
constexpr int DOWN_NNZ_ = N1_ * 4;
constexpr int UP_NNZ_   = N0_ * 3;

// ---------------- device scratch (static, no runtime alloc) ----------------
__device__ float g_buf[4][(size_t)B_ * N0_ * C_];     // T ring (3) + acc (1)
__device__ float g_S[5][(size_t)B_ * N0_ * FIN_];     // encoder T1..T5 (3ch)
__device__ float g_h[(size_t)B_ * N0_ * C_];          // encoder conv output
__device__ float g_hc[(size_t)B_ * N1_ * C_];         // down-pooled
__device__ float g_hc2[(size_t)B_ * N1_ * C_];        // decoder linear output
__device__ float g_z[B_ * Z_];                        // latent
__device__ int   g_rowptr[N0_ + 1];
__device__ int   g_cnt[N0_];                          // in-degree counts (zeroed at END of each call)
__device__ int   g_cur[N0_ + 1];                      // fill cursor
__device__ int   g_srcs[E_];
__device__ float g_norms[E_];
__device__ int2  g_edges[E_];                         // (src, norm bits) for broadcast gather

// ---------------- f32x2 helpers ----------------
__device__ __forceinline__ u64 pack2(float x, float y) {
    u64 r; asm("mov.b64 %0,{%1,%2};" : "=l"(r) : "f"(x), "f"(y)); return r;
}
__device__ __forceinline__ void fma2(u64& acc, u64 a, u64 b) {
    asm("fma.rn.f32x2 %0,%1,%2,%0;" : "+l"(acc) : "l"(a), "l"(b));
}
__device__ __forceinline__ float2 unpack2(u64 v) {
    float2 f; asm("mov.b64 {%0,%1},%2;" : "=f"(f.x), "=f"(f.y) : "l"(v)); return f;
}

// ---------------- CSR build (g_cnt must be zero at entry; restored at call end) ----------------
__global__ void k_count(const int* __restrict__ dst) {
    int e = blockIdx.x * blockDim.x + threadIdx.x;
    if (e < E_) atomicAdd(&g_cnt[dst[e]], 1);
}

__global__ void k_scan() {
    __shared__ int wsum[32];
    __shared__ int carry;
    int t = threadIdx.x;  // 1024 threads
    if (t == 0) carry = 0;
    __syncthreads();
    for (int base = 0; base < N0_; base += 1024) {
        int i = base + t;
        int v = (i < N0_) ? g_cnt[i] : 0;
        int x = v;
#pragma unroll
        for (int d = 1; d < 32; d <<= 1) {
            int y = __shfl_up_sync(0xffffffffu, x, d);
            if ((t & 31) >= d) x += y;
        }
        if ((t & 31) == 31) wsum[t >> 5] = x;
        __syncthreads();
        if (t < 32) {
            int w = wsum[t];
#pragma unroll
            for (int d = 1; d < 32; d <<= 1) {
                int y = __shfl_up_sync(0xffffffffu, w, d);
                if (t >= d) w += y;
            }
            wsum[t] = w;
        }
        __syncthreads();
        int add  = (t >= 32) ? wsum[(t >> 5) - 1] : 0;
        int incl = x + add + carry;
        if (i < N0_) { g_rowptr[i + 1] = incl; g_cur[i + 1] = incl; }
        __syncthreads();
        if (t == 1023) carry = incl;
        __syncthreads();
    }
    if (t == 0) { g_rowptr[0] = 0; g_cur[0] = 0; }
}

__global__ void k_fill(const int* __restrict__ src, const int* __restrict__ dst,
                       const float* __restrict__ norm) {
    int e = blockIdx.x * blockDim.x + threadIdx.x;
    if (e < E_) {
        int d = dst[e];
        int pos = atomicAdd(&g_cur[d], 1);
        g_srcs[pos]  = src[e];
        g_norms[pos] = norm[e];
        g_edges[pos] = make_int2(src[e], __float_as_int(norm[e]));
    }
}

__global__ void k_zero_cnt() {
    int i = blockIdx.x * blockDim.x + threadIdx.x;
    if (i < N0_) g_cnt[i] = 0;
}

// ---------------- encoder conv (Cin=3), unfused propagate (CANARY: unchanged) ----------------
__global__ void enc_prop(const float* __restrict__ x, int prev_idx, int pp_idx, int next_idx) {
    int w = (blockIdx.x * blockDim.x + threadIdx.x) >> 5;
    if (w >= N0_) return;
    int lane = threadIdx.x & 31;
    int b = lane / 3;
    int c = lane - 3 * b;
    bool act = lane < (B_ * FIN_);
    const float* prev = (prev_idx < 0) ? x : g_S[prev_idx];
    bool k1 = (pp_idx == -2);
    const float* pp = k1 ? nullptr : ((pp_idx < 0) ? x : g_S[pp_idx]);

    int beg = g_rowptr[w], end = g_rowptr[w + 1];
    float s = 0.f;
    for (int p0 = beg; p0 < end; p0 += 32) {
        int p = p0 + lane;
        int se = 0; float ne = 0.f;
        if (p < end) { se = g_srcs[p]; ne = g_norms[p]; }
        int cnt = min(32, end - p0);
        for (int j = 0; j < cnt; j++) {
            int   sj = __shfl_sync(0xffffffffu, se, j);
            float nj = __shfl_sync(0xffffffffu, ne, j);
            if (act) s += nj * prev[(b * N0_ + sj) * FIN_ + c];
        }
    }
    if (act) {
        int idx = (b * N0_ + w) * FIN_ + c;
        float tk = k1 ? s : 2.f * s - pp[idx];
        g_S[next_idx][idx] = tk;
    }
}

__global__ void enc_combine(const float* __restrict__ x, const float* __restrict__ Wenc,
                            const float* __restrict__ benc) {
    __shared__ float Wsm[K_ * FIN_ * C_];
    __shared__ float bsm[C_];
    int t = threadIdx.x;
    for (int i = t; i < K_ * FIN_ * C_; i += blockDim.x) Wsm[i] = Wenc[i];
    if (t < C_) bsm[t] = benc[t];
    __syncthreads();
    int w = (blockIdx.x * blockDim.x + t) >> 5;
    if (w >= N0_) return;
    int lane = t & 31;
#pragma unroll
    for (int b = 0; b < B_; b++) {
        float a = bsm[lane];
#pragma unroll
        for (int kc = 0; kc < K_ * FIN_; kc++) {
            int k = kc / 3, c = kc - 3 * (kc / 3);
            float v = (k == 0) ? x[(b * N0_ + w) * FIN_ + c]
                               : g_S[k - 1][(b * N0_ + w) * FIN_ + c];
            a += v * Wsm[kc * C_ + lane];
        }
        g_h[(b * N0_ + w) * C_ + lane] = fmaxf(a, 0.f);
    }
}

// ---------------- pools ----------------
__global__ void down_pool(const int* __restrict__ dcol, const float* __restrict__ dval) {
    int wi = (blockIdx.x * blockDim.x + threadIdx.x) >> 5;
    if (wi >= B_ * N1_) return;
    int lane = threadIdx.x & 31;
    int b = wi / N1_, r = wi - b * N1_;
    float a = 0.f;
#pragma unroll
    for (int j = 0; j < 4; j++) {
        int   col = dcol[4 * r + j];
        float v   = dval[4 * r + j];
        a += v * g_h[(b * N0_ + col) * C_ + lane];
    }
    g_hc[(b * N1_ + r) * C_ + lane] = a;
}

__global__ void up_pool(const int* __restrict__ ucol, const float* __restrict__ uval) {
    int wi = (blockIdx.x * blockDim.x + threadIdx.x) >> 5;
    if (wi >= B_ * N0_) return;
    int lane = threadIdx.x & 31;
    int b = wi / N0_, i = wi - b * N0_;
    float a = 0.f;
#pragma unroll
    for (int j = 0; j < 3; j++) {
        int   col = ucol[3 * i + j];
        float v   = uval[3 * i + j];
        a += v * g_hc2[(b * N1_ + col) * C_ + lane];
    }
    g_buf[0][(b * N0_ + i) * C_ + lane] = a;
}

// ---------------- dense linears (exact R5 versions) ----------------
__global__ void enc_lin_init(const float* __restrict__ bias) {
    int t = blockIdx.x * blockDim.x + threadIdx.x;
    if (t < B_ * Z_) g_z[t] = bias[t & (Z_ - 1)];
}

__global__ void enc_lin(const float* __restrict__ We) {
    constexpr int SLAB = 512;
    __shared__ float hs[B_][SLAB];
    int base = blockIdx.x * SLAB;
    int t = threadIdx.x;  // 128 threads = output channels
    for (int idx = t; idx < B_ * SLAB; idx += 128) {
        int b = idx >> 9, kk = idx & (SLAB - 1);
        int g = base + kk;
        hs[b][kk] = (g < N1_ * C_) ? g_hc[b * (N1_ * C_) + g] : 0.f;
    }
    __syncthreads();
    int lim = min(SLAB, N1_ * C_ - base);
    float a[B_];
#pragma unroll
    for (int b = 0; b < B_; b++) a[b] = 0.f;
#pragma unroll 4
    for (int kk = 0; kk < lim; kk++) {
        float w = We[(size_t)(base + kk) * Z_ + t];
#pragma unroll
        for (int b = 0; b < B_; b++) a[b] += hs[b][kk] * w;
    }
#pragma unroll
    for (int b = 0; b < B_; b++) atomicAdd(&g_z[b * Z_ + t], a[b]);
}

__global__ void dec_lin(const float* __restrict__ Wd, const float* __restrict__ bd) {
    __shared__ float zsm[B_ * Z_];
    int t = threadIdx.x;
    for (int i = t; i < B_ * Z_; i += 256) zsm[i] = g_z[i];
    __syncthreads();
    int j = blockIdx.x * 256 + t;
    if (j >= N1_ * C_) return;
    float bias = bd[j];
    float a[B_];
#pragma unroll
    for (int b = 0; b < B_; b++) a[b] = bias;
#pragma unroll 4
    for (int zk = 0; zk < Z_; zk++) {
        float w = Wd[(size_t)zk * (N1_ * C_) + j];
#pragma unroll
        for (int b = 0; b < B_; b++) a[b] += zsm[b * Z_ + zk] * w;
    }
#pragma unroll
    for (int b = 0; b < B_; b++)
        g_hc2[b * (N1_ * C_) + j] = fmaxf(a[b], 0.f);
}

// ---------------- decoder Cheb conv: k=0 term (smem + f32x2 epilogue) ----------------
template <int COUT, bool HASBIAS>
__global__ void __launch_bounds__(256) conv_k0(
    int t0_idx, float* __restrict__ out3,
    const float* __restrict__ Wk, const float* __restrict__ bias) {
    __shared__ __align__(16) float tkbuf[8][256];
    int w = (blockIdx.x * blockDim.x + threadIdx.x) >> 5;
    if (w >= N0_) return;
    int lane = threadIdx.x & 31;
    int warp = threadIdx.x >> 5;
    bool vlane = lane < COUT;
    u64 w2p[16];
#pragma unroll
    for (int i = 0; i < 16; i++)
        w2p[i] = vlane ? pack2(Wk[(2 * i) * COUT + lane], Wk[(2 * i + 1) * COUT + lane]) : 0ull;
    const float* T0 = g_buf[t0_idx];
#pragma unroll
    for (int b = 0; b < B_; b++)
        tkbuf[warp][b * 32 + lane] = T0[(b * N0_ + w) * C_ + lane];
    __syncwarp();
    float* acc = (COUT == C_) ? g_buf[3] : out3;
#pragma unroll
    for (int b = 0; b < B_; b++) {
        const u64* tb = (const u64*)&tkbuf[warp][b * 32];
        u64 a2 = 0;
#pragma unroll
        for (int i = 0; i < 16; i++) fma2(a2, tb[i], w2p[i]);
        float2 cc = unpack2(a2);
        float contrib = cc.x + cc.y;
        if (vlane)
            acc[(b * N0_ + w) * COUT + lane] = (HASBIAS ? bias[lane] : 0.f) + contrib;
    }
}

// ---------------- fused Cheb step: Tk = 2*prop(Tprev) - Tpp ; acc += Tk @ W[k] ----------------
// gridDim.y = 4: each warp handles 2 batches. Gather via uniform broadcast edge loads
// (no shfl, no staging) + 2 coalesced LDG.32 per edge per batch. Low register pressure.
template <int COUT, bool K1, bool WRITE_T, bool RELU_OUT>
__global__ void __launch_bounds__(256) cheb_step(
    int prev_idx, int pp_idx, int next_idx, int out_idx,
    float* __restrict__ acc3, const float* __restrict__ Wk) {
    __shared__ __align__(16) float tkbuf[8][64];
    int w = (blockIdx.x * blockDim.x + threadIdx.x) >> 5;
    if (w >= N0_) return;
    int lane = threadIdx.x & 31;
    int warp = threadIdx.x >> 5;
    int b0 = blockIdx.y * 2;             // this warp's 2 batches

    const float* Tprev = g_buf[prev_idx] + (size_t)b0 * N0_ * C_ + lane;

    int beg = g_rowptr[w], end = g_rowptr[w + 1];
    float s0 = 0.f, s1 = 0.f;
    int p = beg;
    for (; p + 2 <= end; p += 2) {
        int2 e0 = g_edges[p];            // uniform across warp -> broadcast load
        int2 e1 = g_edges[p + 1];
        float n0 = __int_as_float(e0.y);
        float n1 = __int_as_float(e1.y);
        const float* q0 = Tprev + (size_t)e0.x * C_;
        const float* q1 = Tprev + (size_t)e1.x * C_;
        float a00 = __ldg(q0);
        float a01 = __ldg(q0 + (size_t)N0_ * C_);
        float a10 = __ldg(q1);
        float a11 = __ldg(q1 + (size_t)N0_ * C_);
        s0 = fmaf(n0, a00, s0); s1 = fmaf(n0, a01, s1);
        s0 = fmaf(n1, a10, s0); s1 = fmaf(n1, a11, s1);
    }
    if (p < end) {
        int2 e0 = g_edges[p];
        float n0 = __int_as_float(e0.y);
        const float* q0 = Tprev + (size_t)e0.x * C_;
        s0 = fmaf(n0, __ldg(q0), s0);
        s1 = fmaf(n0, __ldg(q0 + (size_t)N0_ * C_), s1);
    }

    // ---- recursion + stage T_k into smem (and write T_k if needed) ----
    const float* Tpp = K1 ? nullptr : g_buf[pp_idx];
    float* Tnext = WRITE_T ? g_buf[next_idx] : nullptr;
    {
        int base0 = ((b0 + 0) * N0_ + w) * C_;
        int base1 = ((b0 + 1) * N0_ + w) * C_;
        float tk0 = K1 ? s0 : 2.f * s0 - Tpp[base0 + lane];
        float tk1 = K1 ? s1 : 2.f * s1 - Tpp[base1 + lane];
        if (WRITE_T) { Tnext[base0 + lane] = tk0; Tnext[base1 + lane] = tk1; }
        tkbuf[warp][lane]      = tk0;
        tkbuf[warp][32 + lane] = tk1;
    }
    __syncwarp();

    // ---- epilogue (f32x2): contrib[b][cout=lane] = sum_c tk[b][c] * W[c][cout] ----
    bool vlane = lane < COUT;
    u64 w2p[16];
#pragma unroll
    for (int i = 0; i < 16; i++)
        w2p[i] = vlane ? pack2(Wk[(2 * i) * COUT + lane], Wk[(2 * i + 1) * COUT + lane]) : 0ull;
    float* acc  = (COUT == C_) ? g_buf[3] : acc3;
    float* outp = RELU_OUT ? g_buf[out_idx] : nullptr;
#pragma unroll
    for (int b = 0; b < 2; b++) {
        const u64* tb = (const u64*)&tkbuf[warp][b * 32];
        u64 a2 = 0;
#pragma unroll
        for (int i = 0; i < 16; i++) fma2(a2, tb[i], w2p[i]);
        float2 cc = unpack2(a2);
        float contrib = cc.x + cc.y;
        if (RELU_OUT) {
            int base = ((b0 + b) * N0_ + w) * C_;
            float v = acc[base + lane] + contrib;   // COUT==32 here
            outp[base + lane] = fmaxf(v, 0.f);
        } else if (vlane) {
            acc[((b0 + b) * N0_ + w) * COUT + lane] += contrib;
        }
    }
}

// ---------------- launch ----------------
extern "C" void kernel_launch(void* const* d_in, const int* in_sizes, int n_in,
                              void* d_out, int out_size) {
    (void)in_sizes; (void)n_in; (void)out_size;
    const float* x      = (const float*)d_in[0];
    const int*   eidx   = (const int*)  d_in[1];
    const float* Anorm  = (const float*)d_in[2];
    const int*   didx   = (const int*)  d_in[3];
    const float* dval   = (const float*)d_in[4];
    const int*   uidx   = (const int*)  d_in[5];
    const float* uval   = (const float*)d_in[6];
    const float* Wenc0  = (const float*)d_in[7];
    const float* benc0  = (const float*)d_in[8];
    const float* Wdec0  = (const float*)d_in[9];
    const float* bdec0  = (const float*)d_in[10];
    const float* Wdec1  = (const float*)d_in[11];
    const float* encW   = (const float*)d_in[12];
    const float* encb   = (const float*)d_in[13];
    const float* decW   = (const float*)d_in[14];
    const float* decb   = (const float*)d_in[15];
    float* out = (float*)d_out;

    const int GPV  = N0_ * 32 / 256;          // 6250: warp-per-vertex grids
    const dim3 GPV4(GPV, 4);                  // batch-split grids (2 batches/warp)
    const int GE   = (E_ + 255) / 256;        // 1563
    const int GN0  = (N0_ + 255) / 256;       // 196

    // CSR by dst (g_cnt is zero at entry; re-zeroed at end of this call)
    k_count<<<GE, 256>>>(eidx + E_);
    k_scan<<<1, 1024>>>();
    k_fill<<<GE, 256>>>(eidx, eidx + E_, Anorm);

    // ---- encoder conv (Cin=3) ----   (launch idx 5 = third enc_prop: ncu canary)
    enc_prop<<<GPV, 256>>>(x, -1, -2, 0);   // T1
    enc_prop<<<GPV, 256>>>(x,  0, -1, 1);   // T2
    enc_prop<<<GPV, 256>>>(x,  1,  0, 2);   // T3
    enc_prop<<<GPV, 256>>>(x,  2,  1, 3);   // T4
    enc_prop<<<GPV, 256>>>(x,  3,  2, 4);   // T5
    enc_combine<<<GPV, 256>>>(x, Wenc0, benc0);

    // ---- down pool ----
    down_pool<<<B_ * N1_ * 32 / 256, 256>>>(didx + DOWN_NNZ_, dval);

    // ---- encoder linear ----
    enc_lin_init<<<(B_ * Z_ + 255) / 256, 256>>>(encb);
    enc_lin<<<(N1_ * C_ + 511) / 512, 128>>>(encW);

    // ---- decoder linear (+relu) ----
    dec_lin<<<(N1_ * C_ + 255) / 256, 256>>>(decW, decb);

    // ---- up pool -> g_buf[0] ----
    up_pool<<<B_ * N0_ * 32 / 256, 256>>>(uidx + UP_NNZ_, uval);

    // ---- decoder conv0 (32->32, bias, relu). acc = g_buf[3]; ring 0/1/2 ----
    conv_k0<32, true><<<GPV, 256>>>(0, nullptr, Wdec0, bdec0);
    cheb_step<32, true , true , false><<<GPV4, 256>>>(0, 0, 1, 0, nullptr, Wdec0 + 1 * C_ * C_);
    cheb_step<32, false, true , false><<<GPV4, 256>>>(1, 0, 2, 0, nullptr, Wdec0 + 2 * C_ * C_);
    cheb_step<32, false, true , false><<<GPV4, 256>>>(2, 1, 0, 0, nullptr, Wdec0 + 3 * C_ * C_);
    cheb_step<32, false, true , false><<<GPV4, 256>>>(0, 2, 1, 0, nullptr, Wdec0 + 4 * C_ * C_);
    cheb_step<32, false, false, true ><<<GPV4, 256>>>(1, 0, 0, 2, nullptr, Wdec0 + 5 * C_ * C_); // relu -> buf2

    // ---- decoder conv1 (32->3, no bias). acc = d_out; T0 = buf2 ----
    conv_k0<3, false><<<GPV, 256>>>(2, out, Wdec1, nullptr);
    cheb_step<3, true , true , false><<<GPV4, 256>>>(2, 0, 0, 0, out, Wdec1 + 1 * C_ * FIN_);
    cheb_step<3, false, true , false><<<GPV4, 256>>>(0, 2, 1, 0, out, Wdec1 + 2 * C_ * FIN_);
    cheb_step<3, false, true , false><<<GPV4, 256>>>(1, 0, 2, 0, out, Wdec1 + 3 * C_ * FIN_);
    cheb_step<3, false, true , false><<<GPV4, 256>>>(2, 1, 0, 0, out, Wdec1 + 4 * C_ * FIN_);
    cheb_step<3, false, false, false><<<GPV4, 256>>>(0, 2, 0, 0, out, Wdec1 + 5 * C_ * FIN_);

    // restore g_cnt = 0 for the next call (keeps every call identical)
    k_zero_cnt<<<GN0, 256>>>();
}

// round 8
// speedup vs baseline: 1.4811x; 1.1077x over previous
#include <cuda_runtime.h>

typedef unsigned long long u64;

// ---------------- problem constants ----------------
constexpr int B_   = 8;
constexpr int N0_  = 50000;
constexpr int N1_  = 12500;
constexpr int E_   = 400000;
constexpr int FIN_ = 3;
constexpr int C_   = 32;
constexpr int K_   = 6;
constexpr int Z_   = 128;
constexpr int DOWN_NNZ_ = N1_ * 4;
constexpr int UP_NNZ_   = N0_ * 3;

// ---------------- device scratch (static, no runtime alloc) ----------------
__device__ float g_buf[7][(size_t)B_ * N0_ * C_];     // T planes (Cheb ring + relu out)
__device__ float g_S[5][(size_t)B_ * N0_ * FIN_];     // encoder T1..T5 (3ch)
__device__ float g_h[(size_t)B_ * N0_ * C_];          // encoder conv output
__device__ float g_hc[(size_t)B_ * N1_ * C_];         // down-pooled
__device__ float g_hc2[(size_t)B_ * N1_ * C_];        // decoder linear output
__device__ float g_z[B_ * Z_];                        // latent
__device__ int   g_rowptr[N0_ + 1];
__device__ int   g_cnt[N0_];                          // zeroed at END of each call
__device__ int   g_cur[N0_ + 1];                      // fill cursor
__device__ int   g_srcs[E_];
__device__ float g_norms[E_];
__device__ int2  g_edges[E_];                         // (src, norm bits) broadcast gather

// ---------------- f32x2 helpers ----------------
__device__ __forceinline__ u64 pack2(float x, float y) {
    u64 r; asm("mov.b64 %0,{%1,%2};" : "=l"(r) : "f"(x), "f"(y)); return r;
}
__device__ __forceinline__ void fma2(u64& acc, u64 a, u64 b) {
    asm("fma.rn.f32x2 %0,%1,%2,%0;" : "+l"(acc) : "l"(a), "l"(b));
}
__device__ __forceinline__ float2 unpack2(u64 v) {
    float2 f; asm("mov.b64 {%0,%1},%2;" : "=f"(f.x), "=f"(f.y) : "l"(v)); return f;
}

// ---------------- CSR build ----------------
__global__ void k_count(const int* __restrict__ dst) {
    int e = blockIdx.x * blockDim.x + threadIdx.x;
    if (e < E_) atomicAdd(&g_cnt[dst[e]], 1);
}

__global__ void k_scan() {
    __shared__ int wsum[32];
    __shared__ int carry;
    int t = threadIdx.x;  // 1024 threads
    if (t == 0) carry = 0;
    __syncthreads();
    for (int base = 0; base < N0_; base += 1024) {
        int i = base + t;
        int v = (i < N0_) ? g_cnt[i] : 0;
        int x = v;
#pragma unroll
        for (int d = 1; d < 32; d <<= 1) {
            int y = __shfl_up_sync(0xffffffffu, x, d);
            if ((t & 31) >= d) x += y;
        }
        if ((t & 31) == 31) wsum[t >> 5] = x;
        __syncthreads();
        if (t < 32) {
            int w = wsum[t];
#pragma unroll
            for (int d = 1; d < 32; d <<= 1) {
                int y = __shfl_up_sync(0xffffffffu, w, d);
                if (t >= d) w += y;
            }
            wsum[t] = w;
        }
        __syncthreads();
        int add  = (t >= 32) ? wsum[(t >> 5) - 1] : 0;
        int incl = x + add + carry;
        if (i < N0_) { g_rowptr[i + 1] = incl; g_cur[i + 1] = incl; }
        __syncthreads();
        if (t == 1023) carry = incl;
        __syncthreads();
    }
    if (t == 0) { g_rowptr[0] = 0; g_cur[0] = 0; }
}

__global__ void k_fill(const int* __restrict__ src, const int* __restrict__ dst,
                       const float* __restrict__ norm) {
    int e = blockIdx.x * blockDim.x + threadIdx.x;
    if (e < E_) {
        int d = dst[e];
        int pos = atomicAdd(&g_cur[d], 1);
        g_srcs[pos]  = src[e];
        g_norms[pos] = norm[e];
        g_edges[pos] = make_int2(src[e], __float_as_int(norm[e]));
    }
}

__global__ void k_zero_cnt() {
    int i = blockIdx.x * blockDim.x + threadIdx.x;
    if (i < N0_) g_cnt[i] = 0;
}

// ---------------- encoder conv (Cin=3), unfused propagate (CANARY: unchanged) ----------------
__global__ void enc_prop(const float* __restrict__ x, int prev_idx, int pp_idx, int next_idx) {
    int w = (blockIdx.x * blockDim.x + threadIdx.x) >> 5;
    if (w >= N0_) return;
    int lane = threadIdx.x & 31;
    int b = lane / 3;
    int c = lane - 3 * b;
    bool act = lane < (B_ * FIN_);
    const float* prev = (prev_idx < 0) ? x : g_S[prev_idx];
    bool k1 = (pp_idx == -2);
    const float* pp = k1 ? nullptr : ((pp_idx < 0) ? x : g_S[pp_idx]);

    int beg = g_rowptr[w], end = g_rowptr[w + 1];
    float s = 0.f;
    for (int p0 = beg; p0 < end; p0 += 32) {
        int p = p0 + lane;
        int se = 0; float ne = 0.f;
        if (p < end) { se = g_srcs[p]; ne = g_norms[p]; }
        int cnt = min(32, end - p0);
        for (int j = 0; j < cnt; j++) {
            int   sj = __shfl_sync(0xffffffffu, se, j);
            float nj = __shfl_sync(0xffffffffu, ne, j);
            if (act) s += nj * prev[(b * N0_ + sj) * FIN_ + c];
        }
    }
    if (act) {
        int idx = (b * N0_ + w) * FIN_ + c;
        float tk = k1 ? s : 2.f * s - pp[idx];
        g_S[next_idx][idx] = tk;
    }
}

__global__ void enc_combine(const float* __restrict__ x, const float* __restrict__ Wenc,
                            const float* __restrict__ benc) {
    __shared__ float Wsm[K_ * FIN_ * C_];
    __shared__ float bsm[C_];
    int t = threadIdx.x;
    for (int i = t; i < K_ * FIN_ * C_; i += blockDim.x) Wsm[i] = Wenc[i];
    if (t < C_) bsm[t] = benc[t];
    __syncthreads();
    int w = (blockIdx.x * blockDim.x + t) >> 5;
    if (w >= N0_) return;
    int lane = t & 31;
#pragma unroll
    for (int b = 0; b < B_; b++) {
        float a = bsm[lane];
#pragma unroll
        for (int kc = 0; kc < K_ * FIN_; kc++) {
            int k = kc / 3, c = kc - 3 * (kc / 3);
            float v = (k == 0) ? x[(b * N0_ + w) * FIN_ + c]
                               : g_S[k - 1][(b * N0_ + w) * FIN_ + c];
            a += v * Wsm[kc * C_ + lane];
        }
        g_h[(b * N0_ + w) * C_ + lane] = fmaxf(a, 0.f);
    }
}

// ---------------- pools ----------------
__global__ void down_pool(const int* __restrict__ dcol, const float* __restrict__ dval) {
    int wi = (blockIdx.x * blockDim.x + threadIdx.x) >> 5;
    if (wi >= B_ * N1_) return;
    int lane = threadIdx.x & 31;
    int b = wi / N1_, r = wi - b * N1_;
    float a = 0.f;
#pragma unroll
    for (int j = 0; j < 4; j++) {
        int   col = dcol[4 * r + j];
        float v   = dval[4 * r + j];
        a += v * g_h[(b * N0_ + col) * C_ + lane];
    }
    g_hc[(b * N1_ + r) * C_ + lane] = a;
}

__global__ void up_pool(const int* __restrict__ ucol, const float* __restrict__ uval) {
    int wi = (blockIdx.x * blockDim.x + threadIdx.x) >> 5;
    if (wi >= B_ * N0_) return;
    int lane = threadIdx.x & 31;
    int b = wi / N0_, i = wi - b * N0_;
    float a = 0.f;
#pragma unroll
    for (int j = 0; j < 3; j++) {
        int   col = ucol[3 * i + j];
        float v   = uval[3 * i + j];
        a += v * g_hc2[(b * N1_ + col) * C_ + lane];
    }
    g_buf[0][(b * N0_ + i) * C_ + lane] = a;
}

// ---------------- dense linears (unchanged from best) ----------------
__global__ void enc_lin_init(const float* __restrict__ bias) {
    int t = blockIdx.x * blockDim.x + threadIdx.x;
    if (t < B_ * Z_) g_z[t] = bias[t & (Z_ - 1)];
}

__global__ void enc_lin(const float* __restrict__ We) {
    constexpr int SLAB = 512;
    __shared__ float hs[B_][SLAB];
    int base = blockIdx.x * SLAB;
    int t = threadIdx.x;  // 128 threads = output channels
    for (int idx = t; idx < B_ * SLAB; idx += 128) {
        int b = idx >> 9, kk = idx & (SLAB - 1);
        int g = base + kk;
        hs[b][kk] = (g < N1_ * C_) ? g_hc[b * (N1_ * C_) + g] : 0.f;
    }
    __syncthreads();
    int lim = min(SLAB, N1_ * C_ - base);
    float a[B_];
#pragma unroll
    for (int b = 0; b < B_; b++) a[b] = 0.f;
#pragma unroll 4
    for (int kk = 0; kk < lim; kk++) {
        float w = We[(size_t)(base + kk) * Z_ + t];
#pragma unroll
        for (int b = 0; b < B_; b++) a[b] += hs[b][kk] * w;
    }
#pragma unroll
    for (int b = 0; b < B_; b++) atomicAdd(&g_z[b * Z_ + t], a[b]);
}

__global__ void dec_lin(const float* __restrict__ Wd, const float* __restrict__ bd) {
    __shared__ float zsm[B_ * Z_];
    int t = threadIdx.x;
    for (int i = t; i < B_ * Z_; i += 256) zsm[i] = g_z[i];
    __syncthreads();
    int j = blockIdx.x * 256 + t;
    if (j >= N1_ * C_) return;
    float bias = bd[j];
    float a[B_];
#pragma unroll
    for (int b = 0; b < B_; b++) a[b] = bias;
#pragma unroll 4
    for (int zk = 0; zk < Z_; zk++) {
        float w = Wd[(size_t)zk * (N1_ * C_) + j];
#pragma unroll
        for (int b = 0; b < B_; b++) a[b] += zsm[b * Z_ + zk] * w;
    }
#pragma unroll
    for (int b = 0; b < B_; b++)
        g_hc2[b * (N1_ * C_) + j] = fmaxf(a[b], 0.f);
}

// ---------------- pure-gather Cheb step: Tnext = 2*prop(Tprev) - Tpp (K1: = prop) ----------------
// gridDim.y = 4: 2 batches/warp. Broadcast edge loads, 4-edge unroll -> 8 LDG.32 in flight.
template <bool K1>
__global__ void __launch_bounds__(256) cheb_step(int prev_idx, int pp_idx, int next_idx) {
    int w = (blockIdx.x * blockDim.x + threadIdx.x) >> 5;
    if (w >= N0_) return;
    int lane = threadIdx.x & 31;
    int b0 = blockIdx.y * 2;

    const float* Tprev = g_buf[prev_idx] + (size_t)b0 * N0_ * C_ + lane;
    constexpr size_t BSTRIDE = (size_t)N0_ * C_;

    int beg = g_rowptr[w], end = g_rowptr[w + 1];
    float s0 = 0.f, s1 = 0.f;
    int p = beg;
    for (; p + 4 <= end; p += 4) {
        int2 e0 = g_edges[p];
        int2 e1 = g_edges[p + 1];
        int2 e2 = g_edges[p + 2];
        int2 e3 = g_edges[p + 3];
        const float* q0 = Tprev + (size_t)e0.x * C_;
        const float* q1 = Tprev + (size_t)e1.x * C_;
        const float* q2 = Tprev + (size_t)e2.x * C_;
        const float* q3 = Tprev + (size_t)e3.x * C_;
        float a00 = __ldg(q0), a01 = __ldg(q0 + BSTRIDE);
        float a10 = __ldg(q1), a11 = __ldg(q1 + BSTRIDE);
        float a20 = __ldg(q2), a21 = __ldg(q2 + BSTRIDE);
        float a30 = __ldg(q3), a31 = __ldg(q3 + BSTRIDE);
        float n0 = __int_as_float(e0.y), n1 = __int_as_float(e1.y);
        float n2 = __int_as_float(e2.y), n3 = __int_as_float(e3.y);
        s0 = fmaf(n0, a00, s0); s1 = fmaf(n0, a01, s1);
        s0 = fmaf(n1, a10, s0); s1 = fmaf(n1, a11, s1);
        s0 = fmaf(n2, a20, s0); s1 = fmaf(n2, a21, s1);
        s0 = fmaf(n3, a30, s0); s1 = fmaf(n3, a31, s1);
    }
    for (; p < end; p++) {
        int2 e0 = g_edges[p];
        float n0 = __int_as_float(e0.y);
        const float* q0 = Tprev + (size_t)e0.x * C_;
        s0 = fmaf(n0, __ldg(q0), s0);
        s1 = fmaf(n0, __ldg(q0 + BSTRIDE), s1);
    }

    float* Tnext = g_buf[next_idx];
    int base0 = ((b0 + 0) * N0_ + w) * C_ + lane;
    int base1 = ((b0 + 1) * N0_ + w) * C_ + lane;
    if (K1) {
        Tnext[base0] = s0;
        Tnext[base1] = s1;
    } else {
        const float* Tpp = g_buf[pp_idx];
        Tnext[base0] = 2.f * s0 - Tpp[base0];
        Tnext[base1] = 2.f * s1 - Tpp[base1];
    }
}

// ---------------- conv combine: out = [relu]( bias + sum_k T_k @ W_k ) ----------------
// Streaming kernel: warp-per-vertex, all 8 batches; reads 6 T planes coalesced.
template <int COUT, bool HASBIAS, bool RELU>
__global__ void __launch_bounds__(256) conv_combine(
    int i0, int i1, int i2, int i3, int i4, int i5,
    const float* __restrict__ W, const float* __restrict__ bias,
    float* __restrict__ out3, int relu_out_idx) {
    __shared__ __align__(16) float tkbuf[8][256];
    int w = (blockIdx.x * blockDim.x + threadIdx.x) >> 5;
    if (w >= N0_) return;
    int lane = threadIdx.x & 31;
    int warp = threadIdx.x >> 5;
    bool vlane = lane < COUT;

    float acc[B_];
    float binit = (HASBIAS && vlane) ? bias[lane] : 0.f;
#pragma unroll
    for (int b = 0; b < B_; b++) acc[b] = binit;

    int idxs[6] = {i0, i1, i2, i3, i4, i5};
#pragma unroll
    for (int k = 0; k < 6; k++) {
        const float* Tk = g_buf[idxs[k]];
#pragma unroll
        for (int b = 0; b < B_; b++)
            tkbuf[warp][b * 32 + lane] = Tk[(b * N0_ + w) * C_ + lane];
        __syncwarp();
        const float* Wk = W + k * C_ * COUT;
        u64 w2p[16];
#pragma unroll
        for (int i = 0; i < 16; i++)
            w2p[i] = vlane ? pack2(Wk[(2 * i) * COUT + lane], Wk[(2 * i + 1) * COUT + lane]) : 0ull;
#pragma unroll
        for (int b = 0; b < B_; b++) {
            const u64* tb = (const u64*)&tkbuf[warp][b * 32];
            u64 a2 = 0;
#pragma unroll
            for (int i = 0; i < 16; i++) fma2(a2, tb[i], w2p[i]);
            float2 cc = unpack2(a2);
            acc[b] += cc.x + cc.y;
        }
        __syncwarp();
    }

    if (RELU) {
        float* outp = g_buf[relu_out_idx];
#pragma unroll
        for (int b = 0; b < B_; b++)
            outp[(b * N0_ + w) * C_ + lane] = fmaxf(acc[b], 0.f);
    } else {
        if (vlane) {
#pragma unroll
            for (int b = 0; b < B_; b++)
                out3[((size_t)b * N0_ + w) * COUT + lane] = acc[b];
        }
    }
}

// ---------------- launch ----------------
extern "C" void kernel_launch(void* const* d_in, const int* in_sizes, int n_in,
                              void* d_out, int out_size) {
    (void)in_sizes; (void)n_in; (void)out_size;
    const float* x      = (const float*)d_in[0];
    const int*   eidx   = (const int*)  d_in[1];
    const float* Anorm  = (const float*)d_in[2];
    const int*   didx   = (const int*)  d_in[3];
    const float* dval   = (const float*)d_in[4];
    const int*   uidx   = (const int*)  d_in[5];
    const float* uval   = (const float*)d_in[6];
    const float* Wenc0  = (const float*)d_in[7];
    const float* benc0  = (const float*)d_in[8];
    const float* Wdec0  = (const float*)d_in[9];
    const float* bdec0  = (const float*)d_in[10];
    const float* Wdec1  = (const float*)d_in[11];
    const float* encW   = (const float*)d_in[12];
    const float* encb   = (const float*)d_in[13];
    const float* decW   = (const float*)d_in[14];
    const float* decb   = (const float*)d_in[15];
    float* out = (float*)d_out;

    const int GPV  = N0_ * 32 / 256;          // 6250: warp-per-vertex grids
    const dim3 GPV4(GPV, 4);                  // batch-split (2 batches/warp)
    const int GE   = (E_ + 255) / 256;
    const int GN0  = (N0_ + 255) / 256;

    // CSR by dst (g_cnt zero at entry; re-zeroed at end of call)
    k_count<<<GE, 256>>>(eidx + E_);
    k_scan<<<1, 1024>>>();
    k_fill<<<GE, 256>>>(eidx, eidx + E_, Anorm);

    // ---- encoder conv (Cin=3) ----   (launch idx 5 = third enc_prop: ncu canary)
    enc_prop<<<GPV, 256>>>(x, -1, -2, 0);   // T1
    enc_prop<<<GPV, 256>>>(x,  0, -1, 1);   // T2
    enc_prop<<<GPV, 256>>>(x,  1,  0, 2);   // T3
    enc_prop<<<GPV, 256>>>(x,  2,  1, 3);   // T4
    enc_prop<<<GPV, 256>>>(x,  3,  2, 4);   // T5
    enc_combine<<<GPV, 256>>>(x, Wenc0, benc0);

    // ---- down pool ----
    down_pool<<<B_ * N1_ * 32 / 256, 256>>>(didx + DOWN_NNZ_, dval);

    // ---- encoder linear ----
    enc_lin_init<<<(B_ * Z_ + 255) / 256, 256>>>(encb);
    enc_lin<<<(N1_ * C_ + 511) / 512, 128>>>(encW);

    // ---- decoder linear (+relu) ----
    dec_lin<<<(N1_ * C_ + 255) / 256, 256>>>(decW, decb);

    // ---- up pool -> g_buf[0] (= T0 of conv0) ----
    up_pool<<<B_ * N0_ * 32 / 256, 256>>>(uidx + UP_NNZ_, uval);

    // ---- decoder conv0: T1..T5 -> g_buf[1..5]; combine -> relu -> g_buf[6] ----
    cheb_step<true ><<<GPV4, 256>>>(0, 0, 1);
    cheb_step<false><<<GPV4, 256>>>(1, 0, 2);
    cheb_step<false><<<GPV4, 256>>>(2, 1, 3);
    cheb_step<false><<<GPV4, 256>>>(3, 2, 4);
    cheb_step<false><<<GPV4, 256>>>(4, 3, 5);
    conv_combine<32, true, true><<<GPV, 256>>>(0, 1, 2, 3, 4, 5, Wdec0, bdec0, nullptr, 6);

    // ---- decoder conv1: T0 = g_buf[6]; T1..T5 -> g_buf[0..4]; combine -> d_out ----
    cheb_step<true ><<<GPV4, 256>>>(6, 0, 0);
    cheb_step<false><<<GPV4, 256>>>(0, 6, 1);
    cheb_step<false><<<GPV4, 256>>>(1, 0, 2);
    cheb_step<false><<<GPV4, 256>>>(2, 1, 3);
    cheb_step<false><<<GPV4, 256>>>(3, 2, 4);
    conv_combine<3, false, false><<<GPV, 256>>>(6, 0, 1, 2, 3, 4, Wdec1, nullptr, out, 0);

    // restore g_cnt = 0 for next call
    k_zero_cnt<<<GN0, 256>>>();
}